// round 1
// baseline (speedup 1.0000x reference)
#include <cuda_runtime.h>

// Shapes: x [4,2048,1024] f32, W [1024,3072] f32, b [3072] f32
// out [4,16,2048,64] f32 = scale * Q (K^T V),  scale = 32
#define M_TOT 8192
#define K_DIM 1024
#define N_TOT 3072
#define BH    64
#define SEQ   2048
#define HD    64
#define NSPLIT 8

// Scratch (device globals; no runtime allocation allowed)
__device__ float g_Q[BH * SEQ * HD];               // 32 MB
__device__ float g_K[BH * SEQ * HD];               // 32 MB
__device__ float g_V[BH * SEQ * HD];               // 32 MB
__device__ float g_KtVp[BH * NSPLIT * HD * HD];    // 8 MB partials
__device__ float g_KtV[BH * HD * HD];              // 1 MB (scale folded in)

// ---------------------------------------------------------------------------
// Stage 1: qkv = x @ W + b, scattered into Q/K/V [bh][n][d]
// 128x128 block tile, BK=16, 256 threads, 8x8 per-thread (split 4+4 pattern)
// ---------------------------------------------------------------------------
__global__ __launch_bounds__(256) void qkv_gemm(const float* __restrict__ x,
                                                const float* __restrict__ W,
                                                const float* __restrict__ bias) {
    __shared__ float As[16][128];   // [k][m] (transposed on load)
    __shared__ float Bs[16][128];   // [k][n]
    const int bm = blockIdx.y * 128;
    const int bn = blockIdx.x * 128;
    const int tid = threadIdx.x;
    const int tx = tid & 15, ty = tid >> 4;

    float acc[8][8];
#pragma unroll
    for (int i = 0; i < 8; i++)
#pragma unroll
        for (int j = 0; j < 8; j++) acc[i][j] = 0.f;

    for (int k0 = 0; k0 < K_DIM; k0 += 16) {
        // A tile: 128 rows x 16 k; 512 float4, 2 per thread, transpose into As
#pragma unroll
        for (int i = 0; i < 2; i++) {
            int idx = tid + i * 256;
            int r = idx >> 2, c4 = (idx & 3) << 2;
            float4 v = *(const float4*)&x[(bm + r) * K_DIM + k0 + c4];
            As[c4 + 0][r] = v.x; As[c4 + 1][r] = v.y;
            As[c4 + 2][r] = v.z; As[c4 + 3][r] = v.w;
        }
        // B tile: 16 k x 128 n; 512 float4, 2 per thread
#pragma unroll
        for (int i = 0; i < 2; i++) {
            int idx = tid + i * 256;
            int r = idx >> 5, c4 = (idx & 31) << 2;
            *(float4*)&Bs[r][c4] = *(const float4*)&W[(k0 + r) * N_TOT + bn + c4];
        }
        __syncthreads();

#pragma unroll
        for (int kk = 0; kk < 16; kk++) {
            float ra[8], rb[8];
            *(float4*)&ra[0] = *(float4*)&As[kk][ty * 4];
            *(float4*)&ra[4] = *(float4*)&As[kk][64 + ty * 4];
            *(float4*)&rb[0] = *(float4*)&Bs[kk][tx * 4];
            *(float4*)&rb[4] = *(float4*)&Bs[kk][64 + tx * 4];
#pragma unroll
            for (int i = 0; i < 8; i++)
#pragma unroll
                for (int j = 0; j < 8; j++)
                    acc[i][j] = fmaf(ra[i], rb[j], acc[i][j]);
        }
        __syncthreads();
    }

    // Epilogue: add bias, decode j = h*192 + d*3 + c, scatter into Q/K/V
#pragma unroll
    for (int i = 0; i < 8; i++) {
        int m = bm + ((i < 4) ? (ty * 4 + i) : (64 + ty * 4 + (i - 4)));
        int b = m >> 11, n = m & 2047;
#pragma unroll
        for (int j = 0; j < 8; j++) {
            int jc = bn + ((j < 4) ? (tx * 4 + j) : (64 + tx * 4 + (j - 4)));
            float val = acc[i][j] + bias[jc];
            int c  = jc % 3;
            int hd = jc / 3;
            int d  = hd & 63, h = hd >> 6;
            int idx = (((b << 4) + h) * SEQ + n) * HD + d;
            float* dst = (c == 0) ? g_Q : (c == 1) ? g_K : g_V;
            dst[idx] = val;
        }
    }
}

// ---------------------------------------------------------------------------
// Stage 2: per (bh, split): partial K^T V over a 256-row n-chunk.
// grid (NSPLIT, BH), 256 threads, 4x4 per-thread over the 64x64 output.
// ---------------------------------------------------------------------------
__global__ __launch_bounds__(256) void ktv_partial() {
    const int sp = blockIdx.x, bh = blockIdx.y;
    const float* Kp = g_K + bh * SEQ * HD;
    const float* Vp = g_V + bh * SEQ * HD;
    __shared__ float Ks[32][64];
    __shared__ float Vs[32][64];
    const int tid = threadIdx.x;
    const int d1 = (tid >> 4) << 2;
    const int d2 = (tid & 15) << 2;
    float acc[4][4] = {};

    const int nbase = sp * (SEQ / NSPLIT);
    for (int n0 = nbase; n0 < nbase + SEQ / NSPLIT; n0 += 32) {
#pragma unroll
        for (int i = 0; i < 2; i++) {
            int idx = tid + i * 256;
            int r = idx >> 4, c4 = (idx & 15) << 2;
            *(float4*)&Ks[r][c4] = *(const float4*)&Kp[(n0 + r) * HD + c4];
            *(float4*)&Vs[r][c4] = *(const float4*)&Vp[(n0 + r) * HD + c4];
        }
        __syncthreads();
#pragma unroll
        for (int n = 0; n < 32; n++) {
            float4 a = *(float4*)&Ks[n][d1];
            float4 b = *(float4*)&Vs[n][d2];
            float av[4] = {a.x, a.y, a.z, a.w};
            float bv[4] = {b.x, b.y, b.z, b.w};
#pragma unroll
            for (int i = 0; i < 4; i++)
#pragma unroll
                for (int j = 0; j < 4; j++)
                    acc[i][j] = fmaf(av[i], bv[j], acc[i][j]);
        }
        __syncthreads();
    }
#pragma unroll
    for (int i = 0; i < 4; i++)
#pragma unroll
        for (int j = 0; j < 4; j++)
            g_KtVp[((bh * NSPLIT + sp) * HD + d1 + i) * HD + d2 + j] = acc[i][j];
}

// ---------------------------------------------------------------------------
// Stage 3: reduce the NSPLIT partials, fold in scale = 32 (deterministic).
// ---------------------------------------------------------------------------
__global__ __launch_bounds__(256) void ktv_reduce() {
    int i = blockIdx.x * 256 + threadIdx.x;     // BH*4096 total
    int bh = i >> 12, rc = i & 4095;
    float s = 0.f;
#pragma unroll
    for (int sp = 0; sp < NSPLIT; sp++)
        s += g_KtVp[(bh * NSPLIT + sp) * 4096 + rc];
    g_KtV[i] = 32.0f * s;
}

// ---------------------------------------------------------------------------
// Stage 4: out[bh][n][d] = Q[bh][n][:] @ KtV[bh][:][d]
// grid (SEQ/64, BH), 256 threads, 4 rows x 4 cols per thread.
// ---------------------------------------------------------------------------
__global__ __launch_bounds__(256) void out_gemm(float* __restrict__ out) {
    const int bh = blockIdx.y;
    const int n0 = blockIdx.x * 64;
    __shared__ float Qs[64][64];   // [n][e]
    __shared__ float Ms[64][64];   // KtV [e][d]
    const int tid = threadIdx.x;

#pragma unroll
    for (int i = 0; i < 4; i++) {
        int idx = tid + i * 256;
        int r = idx >> 4, c4 = (idx & 15) << 2;
        *(float4*)&Ms[r][c4] = *(const float4*)&g_KtV[(bh * HD + r) * HD + c4];
        *(float4*)&Qs[r][c4] = *(const float4*)&g_Q[(bh * SEQ + n0 + r) * HD + c4];
    }
    __syncthreads();

    const int r0 = (tid >> 4) << 2;
    const int c0 = (tid & 15) << 2;
    float acc[4][4] = {};
#pragma unroll
    for (int e = 0; e < 64; e++) {
        float4 b = *(float4*)&Ms[e][c0];
        float bv[4] = {b.x, b.y, b.z, b.w};
        float av[4] = {Qs[r0][e], Qs[r0 + 1][e], Qs[r0 + 2][e], Qs[r0 + 3][e]};
#pragma unroll
        for (int i = 0; i < 4; i++)
#pragma unroll
            for (int j = 0; j < 4; j++)
                acc[i][j] = fmaf(av[i], bv[j], acc[i][j]);
    }
#pragma unroll
    for (int i = 0; i < 4; i++) {
        float4 v = make_float4(acc[i][0], acc[i][1], acc[i][2], acc[i][3]);
        *(float4*)&out[(bh * SEQ + n0 + r0 + i) * HD + c0] = v;
    }
}

// ---------------------------------------------------------------------------
extern "C" void kernel_launch(void* const* d_in, const int* in_sizes, int n_in,
                              void* d_out, int out_size) {
    const float* x = (const float*)d_in[0];   // [4,2048,1024]
    const float* W = (const float*)d_in[1];   // [1024,3072]
    const float* b = (const float*)d_in[2];   // [3072]
    float* out = (float*)d_out;               // [4,16,2048,64]

    qkv_gemm  <<<dim3(N_TOT / 128, M_TOT / 128), 256>>>(x, W, b);
    ktv_partial<<<dim3(NSPLIT, BH), 256>>>();
    ktv_reduce <<<(BH * HD * HD) / 256, 256>>>();
    out_gemm  <<<dim3(SEQ / 64, BH), 256>>>(out);
}

// round 2
// speedup vs baseline: 1.3166x; 1.3166x over previous
#include <cuda_runtime.h>
#include <cuda_bf16.h>
#include <cstdint>

// Shapes: x [4,2048,1024] f32, W [1024,3072] f32, b [3072] f32
// out [4,16,2048,64] f32 = scale * Q (K^T V),  scale = 32
#define M_TOT 8192
#define K_DIM 1024
#define N_TOT 3072
#define BH    64
#define SEQ   2048
#define HD    64
#define NSPLIT 8

#define BM 128
#define BN 96
#define BK 32

// Scratch (device globals; no runtime allocation allowed)
__device__ float g_Q[BH * SEQ * HD];               // 32 MB
__device__ float g_K[BH * SEQ * HD];               // 32 MB
__device__ float g_V[BH * SEQ * HD];               // 32 MB
__device__ float g_KtVp[BH * NSPLIT * HD * HD];    // 8 MB partials
__device__ float g_KtV[BH * HD * HD];              // 1 MB (scale folded in)

// ---------------------------------------------------------------------------
// bf16 split helpers: f = hi + lo with hi = bf16(f), lo = bf16(f - hi)
// ---------------------------------------------------------------------------
__device__ __forceinline__ void split2(float a, float b, uint32_t& hi, uint32_t& lo) {
    __nv_bfloat16 ah = __float2bfloat16_rn(a);
    __nv_bfloat16 bh = __float2bfloat16_rn(b);
    float ares = a - __bfloat162float(ah);
    float bres = b - __bfloat162float(bh);
    __nv_bfloat16 al = __float2bfloat16_rn(ares);
    __nv_bfloat16 bl = __float2bfloat16_rn(bres);
    hi = (uint32_t)(*reinterpret_cast<uint16_t*>(&ah)) |
         ((uint32_t)(*reinterpret_cast<uint16_t*>(&bh)) << 16);
    lo = (uint32_t)(*reinterpret_cast<uint16_t*>(&al)) |
         ((uint32_t)(*reinterpret_cast<uint16_t*>(&bl)) << 16);
}

__device__ __forceinline__ void mma_bf16(float* c, const uint32_t* a, const uint32_t* b) {
    asm volatile(
        "mma.sync.aligned.m16n8k16.row.col.f32.bf16.bf16.f32 "
        "{%0,%1,%2,%3}, {%4,%5,%6,%7}, {%8,%9}, {%0,%1,%2,%3};"
        : "+f"(c[0]), "+f"(c[1]), "+f"(c[2]), "+f"(c[3])
        : "r"(a[0]), "r"(a[1]), "r"(a[2]), "r"(a[3]), "r"(b[0]), "r"(b[1]));
}

// ---------------------------------------------------------------------------
// Stage 1: qkv = x @ W + b (tensor cores, 3x-bf16 split), scatter to Q/K/V.
// Block tile 128x96, BK=32, 256 threads = 8 warps (2 m-rows x 4 n-cols),
// warp tile 64x24 (4 m-frags x 3 n-frags of m16n8k16).
// BN=96 => each block's n-range lies inside ONE head (192-wide j-region).
// ---------------------------------------------------------------------------
__global__ __launch_bounds__(256, 1) void qkv_gemm_tc(const float* __restrict__ x,
                                                      const float* __restrict__ W,
                                                      const float* __restrict__ bias) {
    // Operands in shared as packed bf16 k-pairs (u32). Row strides padded.
    __shared__ uint32_t Ap_h[BM][18];  // [m][kpair], 16 pairs used
    __shared__ uint32_t Ap_l[BM][18];
    __shared__ uint32_t Bp_h[BN][17];  // [n][kpair]
    __shared__ uint32_t Bp_l[BN][17];

    const int tid = threadIdx.x;
    const int wid = tid >> 5;
    const int lane = tid & 31;
    const int wm = wid >> 2;          // 0..1
    const int wn = wid & 3;           // 0..3
    const int r = lane >> 2;          // 0..7
    const int c = lane & 3;           // 0..3

    const int bm = blockIdx.y * BM;
    const int bn = blockIdx.x * BN;

    float acc[4][3][4];
#pragma unroll
    for (int i = 0; i < 4; i++)
#pragma unroll
        for (int j = 0; j < 3; j++)
#pragma unroll
            for (int k = 0; k < 4; k++) acc[i][j][k] = 0.f;

    float4 ar[4];
    float2 br0[3], br1[3];

    // --- staging helpers (inlined manually) ---
    // A: idx = tid + i*256 ; m = idx>>3, k4 = (idx&7)*4   (128x32 floats)
    // B: unit u = tid + i*256 ; n2 = u%48 (n pair), kp = u/48 (k pair) (16x48 units)

#define LOAD_TILE(K0)                                                              \
    {                                                                              \
        _Pragma("unroll")                                                          \
        for (int i = 0; i < 4; i++) {                                              \
            int idx = tid + i * 256;                                               \
            int m = idx >> 3, k4 = (idx & 7) << 2;                                 \
            ar[i] = *(const float4*)&x[(size_t)(bm + m) * K_DIM + (K0) + k4];      \
        }                                                                          \
        _Pragma("unroll")                                                          \
        for (int i = 0; i < 3; i++) {                                              \
            int u = tid + i * 256;                                                 \
            int n2 = u % 48, kp = u / 48;                                          \
            const float* p = &W[(size_t)((K0) + 2 * kp) * N_TOT + bn + 2 * n2];    \
            br0[i] = *(const float2*)p;                                            \
            br1[i] = *(const float2*)(p + N_TOT);                                  \
        }                                                                          \
    }

#define STORE_TILE()                                                               \
    {                                                                              \
        _Pragma("unroll")                                                          \
        for (int i = 0; i < 4; i++) {                                              \
            int idx = tid + i * 256;                                               \
            int m = idx >> 3, k4 = (idx & 7) << 2;                                 \
            uint32_t h0, l0, h1, l1;                                               \
            split2(ar[i].x, ar[i].y, h0, l0);                                      \
            split2(ar[i].z, ar[i].w, h1, l1);                                      \
            int kp = k4 >> 1;                                                      \
            Ap_h[m][kp] = h0; Ap_h[m][kp + 1] = h1;                                \
            Ap_l[m][kp] = l0; Ap_l[m][kp + 1] = l1;                                \
        }                                                                          \
        _Pragma("unroll")                                                          \
        for (int i = 0; i < 3; i++) {                                              \
            int u = tid + i * 256;                                                 \
            int n2 = u % 48, kp = u / 48;                                          \
            uint32_t h, l;                                                         \
            split2(br0[i].x, br1[i].x, h, l);  /* (k, k+1) for n = 2*n2   */       \
            Bp_h[2 * n2][kp] = h; Bp_l[2 * n2][kp] = l;                            \
            split2(br0[i].y, br1[i].y, h, l);  /* (k, k+1) for n = 2*n2+1 */       \
            Bp_h[2 * n2 + 1][kp] = h; Bp_l[2 * n2 + 1][kp] = l;                    \
        }                                                                          \
    }

    LOAD_TILE(0);
    STORE_TILE();
    __syncthreads();

    for (int t = 0; t < K_DIM / BK; t++) {
        if (t < K_DIM / BK - 1) LOAD_TILE((t + 1) * BK);

        // compute 2 k16-steps from shared
#pragma unroll
        for (int ks = 0; ks < 2; ks++) {
            uint32_t a_h[4][4], a_l[4][4];
#pragma unroll
            for (int mf = 0; mf < 4; mf++) {
                int m0 = wm * 64 + mf * 16 + r;
                int kp = ks * 8 + c;
                a_h[mf][0] = Ap_h[m0][kp];
                a_h[mf][1] = Ap_h[m0 + 8][kp];
                a_h[mf][2] = Ap_h[m0][kp + 4];
                a_h[mf][3] = Ap_h[m0 + 8][kp + 4];
                a_l[mf][0] = Ap_l[m0][kp];
                a_l[mf][1] = Ap_l[m0 + 8][kp];
                a_l[mf][2] = Ap_l[m0][kp + 4];
                a_l[mf][3] = Ap_l[m0 + 8][kp + 4];
            }
            uint32_t b_h[3][2], b_l[3][2];
#pragma unroll
            for (int nf = 0; nf < 3; nf++) {
                int n0 = wn * 24 + nf * 8 + r;
                int kp = ks * 8 + c;
                b_h[nf][0] = Bp_h[n0][kp];
                b_h[nf][1] = Bp_h[n0][kp + 4];
                b_l[nf][0] = Bp_l[n0][kp];
                b_l[nf][1] = Bp_l[n0][kp + 4];
            }
            // 3 split terms; 12 independent mma between accumulator reuses
#pragma unroll
            for (int mf = 0; mf < 4; mf++)
#pragma unroll
                for (int nf = 0; nf < 3; nf++) mma_bf16(acc[mf][nf], a_h[mf], b_h[nf]);
#pragma unroll
            for (int mf = 0; mf < 4; mf++)
#pragma unroll
                for (int nf = 0; nf < 3; nf++) mma_bf16(acc[mf][nf], a_h[mf], b_l[nf]);
#pragma unroll
            for (int mf = 0; mf < 4; mf++)
#pragma unroll
                for (int nf = 0; nf < 3; nf++) mma_bf16(acc[mf][nf], a_l[mf], b_h[nf]);
        }

        __syncthreads();
        if (t < K_DIM / BK - 1) {
            STORE_TILE();
            __syncthreads();
        }
    }

    // Epilogue: bias + decode jc = h*192 + d*3 + cc, scatter into Q/K/V.
    // Whole block lies in one head; writes hit a 32-wide contiguous d-window.
#pragma unroll
    for (int nf = 0; nf < 3; nf++) {
#pragma unroll
        for (int i1 = 0; i1 < 2; i1++) {  // column sub-index (c0/c1)
            int jc = bn + wn * 24 + nf * 8 + c * 2 + i1;
            float bv = __ldg(&bias[jc]);
            int cc = jc % 3;
            int hd = jc / 3;
            int d = hd & 63, h = hd >> 6;
            float* dst = (cc == 0) ? g_Q : (cc == 1) ? g_K : g_V;
#pragma unroll
            for (int mf = 0; mf < 4; mf++) {
#pragma unroll
                for (int i2 = 0; i2 < 2; i2++) {  // row sub-index (+0/+8)
                    int m = bm + wm * 64 + mf * 16 + r + i2 * 8;
                    int b = m >> 11, n = m & 2047;
                    float val = acc[mf][nf][i2 * 2 + i1] + bv;
                    int idx = (((b << 4) + h) * SEQ + n) * HD + d;
                    dst[idx] = val;
                }
            }
        }
    }
#undef LOAD_TILE
#undef STORE_TILE
}

// ---------------------------------------------------------------------------
// Stage 2: per (bh, split): partial K^T V over a 256-row n-chunk.
// ---------------------------------------------------------------------------
__global__ __launch_bounds__(256) void ktv_partial() {
    const int sp = blockIdx.x, bh = blockIdx.y;
    const float* Kp = g_K + bh * SEQ * HD;
    const float* Vp = g_V + bh * SEQ * HD;
    __shared__ float Ks[32][64];
    __shared__ float Vs[32][64];
    const int tid = threadIdx.x;
    const int d1 = (tid >> 4) << 2;
    const int d2 = (tid & 15) << 2;
    float acc[4][4] = {};

    const int nbase = sp * (SEQ / NSPLIT);
    for (int n0 = nbase; n0 < nbase + SEQ / NSPLIT; n0 += 32) {
#pragma unroll
        for (int i = 0; i < 2; i++) {
            int idx = tid + i * 256;
            int rr = idx >> 4, c4 = (idx & 15) << 2;
            *(float4*)&Ks[rr][c4] = *(const float4*)&Kp[(n0 + rr) * HD + c4];
            *(float4*)&Vs[rr][c4] = *(const float4*)&Vp[(n0 + rr) * HD + c4];
        }
        __syncthreads();
#pragma unroll
        for (int n = 0; n < 32; n++) {
            float4 a = *(float4*)&Ks[n][d1];
            float4 b = *(float4*)&Vs[n][d2];
            float av[4] = {a.x, a.y, a.z, a.w};
            float bv[4] = {b.x, b.y, b.z, b.w};
#pragma unroll
            for (int i = 0; i < 4; i++)
#pragma unroll
                for (int j = 0; j < 4; j++)
                    acc[i][j] = fmaf(av[i], bv[j], acc[i][j]);
        }
        __syncthreads();
    }
#pragma unroll
    for (int i = 0; i < 4; i++)
#pragma unroll
        for (int j = 0; j < 4; j++)
            g_KtVp[((bh * NSPLIT + sp) * HD + d1 + i) * HD + d2 + j] = acc[i][j];
}

// ---------------------------------------------------------------------------
// Stage 3: reduce the NSPLIT partials, fold in scale = 32 (deterministic).
// ---------------------------------------------------------------------------
__global__ __launch_bounds__(256) void ktv_reduce() {
    int i = blockIdx.x * 256 + threadIdx.x;
    int bh = i >> 12, rc = i & 4095;
    float s = 0.f;
#pragma unroll
    for (int sp = 0; sp < NSPLIT; sp++)
        s += g_KtVp[(bh * NSPLIT + sp) * 4096 + rc];
    g_KtV[i] = 32.0f * s;
}

// ---------------------------------------------------------------------------
// Stage 4: out[bh][n][d] = Q[bh][n][:] @ KtV[bh][:][d]
// ---------------------------------------------------------------------------
__global__ __launch_bounds__(256) void out_gemm(float* __restrict__ out) {
    const int bh = blockIdx.y;
    const int n0 = blockIdx.x * 64;
    __shared__ float Qs[64][64];
    __shared__ float Ms[64][64];
    const int tid = threadIdx.x;

#pragma unroll
    for (int i = 0; i < 4; i++) {
        int idx = tid + i * 256;
        int rr = idx >> 4, c4 = (idx & 15) << 2;
        *(float4*)&Ms[rr][c4] = *(const float4*)&g_KtV[(bh * HD + rr) * HD + c4];
        *(float4*)&Qs[rr][c4] = *(const float4*)&g_Q[(bh * SEQ + n0 + rr) * HD + c4];
    }
    __syncthreads();

    const int r0 = (tid >> 4) << 2;
    const int c0 = (tid & 15) << 2;
    float acc[4][4] = {};
#pragma unroll
    for (int e = 0; e < 64; e++) {
        float4 b = *(float4*)&Ms[e][c0];
        float bv[4] = {b.x, b.y, b.z, b.w};
        float av[4] = {Qs[r0][e], Qs[r0 + 1][e], Qs[r0 + 2][e], Qs[r0 + 3][e]};
#pragma unroll
        for (int i = 0; i < 4; i++)
#pragma unroll
            for (int j = 0; j < 4; j++)
                acc[i][j] = fmaf(av[i], bv[j], acc[i][j]);
    }
#pragma unroll
    for (int i = 0; i < 4; i++) {
        float4 v = make_float4(acc[i][0], acc[i][1], acc[i][2], acc[i][3]);
        *(float4*)&out[(bh * SEQ + n0 + r0 + i) * HD + c0] = v;
    }
}

// ---------------------------------------------------------------------------
extern "C" void kernel_launch(void* const* d_in, const int* in_sizes, int n_in,
                              void* d_out, int out_size) {
    const float* x = (const float*)d_in[0];   // [4,2048,1024]
    const float* W = (const float*)d_in[1];   // [1024,3072]
    const float* b = (const float*)d_in[2];   // [3072]
    float* out = (float*)d_out;               // [4,16,2048,64]

    qkv_gemm_tc<<<dim3(N_TOT / BN, M_TOT / BM), 256>>>(x, W, b);
    ktv_partial<<<dim3(NSPLIT, BH), 256>>>();
    ktv_reduce<<<(BH * HD * HD) / 256, 256>>>();
    out_gemm<<<dim3(SEQ / 64, BH), 256>>>(out);
}

// round 3
// speedup vs baseline: 1.8365x; 1.3948x over previous
#include <cuda_runtime.h>
#include <cuda_bf16.h>
#include <cstdint>

// Shapes: x [4,2048,1024] f32, W [1024,3072] f32, b [3072] f32
// out [4,16,2048,64] f32 = scale * Q (K^T V),  scale = 32
#define M_TOT 8192
#define K_DIM 1024
#define N_TOT 3072
#define K3    3072        // 3*K_DIM: [hi|hi|lo] x  vs  [hi|lo|hi] w
#define BH    64
#define SEQ   2048
#define HD    64
#define NSPLIT 8

#define GBM 128
#define GBN 128
#define GBK 32            // bf16 elements per k-stage
#define APAD 8            // row pad -> 40 bf16 = 80B stride (bank-conflict-free ldmatrix)
#define NITER (K3 / GBK)  // 96

// Scratch (device globals; no runtime allocation allowed)
__device__ __nv_bfloat16 g_Xp[(size_t)M_TOT * K3];   // 50.3 MB
__device__ __nv_bfloat16 g_Wt[(size_t)N_TOT * K3];   // 18.9 MB
__device__ float g_Q[BH * SEQ * HD];                 // 32 MB
__device__ float g_K[BH * SEQ * HD];                 // 32 MB
__device__ float g_V[BH * SEQ * HD];                 // 32 MB
__device__ float g_KtVp[BH * NSPLIT * HD * HD];      // 8 MB
__device__ float g_KtV[BH * HD * HD];                // 1 MB

// ---------------------------------------------------------------------------
__device__ __forceinline__ void split2(float a, float b, uint32_t& hi, uint32_t& lo) {
    __nv_bfloat16 ah = __float2bfloat16_rn(a);
    __nv_bfloat16 bh = __float2bfloat16_rn(b);
    __nv_bfloat16 al = __float2bfloat16_rn(a - __bfloat162float(ah));
    __nv_bfloat16 bl = __float2bfloat16_rn(b - __bfloat162float(bh));
    hi = (uint32_t)(*reinterpret_cast<uint16_t*>(&ah)) |
         ((uint32_t)(*reinterpret_cast<uint16_t*>(&bh)) << 16);
    lo = (uint32_t)(*reinterpret_cast<uint16_t*>(&al)) |
         ((uint32_t)(*reinterpret_cast<uint16_t*>(&bl)) << 16);
}

__device__ __forceinline__ void mma_bf16(float* c, const uint32_t* a, const uint32_t* b) {
    asm volatile(
        "mma.sync.aligned.m16n8k16.row.col.f32.bf16.bf16.f32 "
        "{%0,%1,%2,%3}, {%4,%5,%6,%7}, {%8,%9}, {%0,%1,%2,%3};"
        : "+f"(c[0]), "+f"(c[1]), "+f"(c[2]), "+f"(c[3])
        : "r"(a[0]), "r"(a[1]), "r"(a[2]), "r"(a[3]), "r"(b[0]), "r"(b[1]));
}

__device__ __forceinline__ void ldsm_x4(uint32_t* r, const void* p) {
    uint32_t a = (uint32_t)__cvta_generic_to_shared(p);
    asm volatile("ldmatrix.sync.aligned.m8n8.x4.shared.b16 {%0,%1,%2,%3}, [%4];"
                 : "=r"(r[0]), "=r"(r[1]), "=r"(r[2]), "=r"(r[3]) : "r"(a));
}

__device__ __forceinline__ void cp16(void* smem, const void* gmem) {
    uint32_t s = (uint32_t)__cvta_generic_to_shared(smem);
    asm volatile("cp.async.cg.shared.global [%0], [%1], 16;" :: "r"(s), "l"(gmem));
}

// ---------------------------------------------------------------------------
// Precompute: x [M][K] f32 -> Xp [M][3K] bf16 = [hi | hi | lo]
// ---------------------------------------------------------------------------
__global__ __launch_bounds__(256) void split_x(const float* __restrict__ x) {
    int i = blockIdx.x * 256 + threadIdx.x;          // M*K/4 threads
    int m = i >> 8, k4 = (i & 255) << 2;
    float4 v = *(const float4*)&x[(size_t)m * K_DIM + k4];
    uint32_t h01, l01, h23, l23;
    split2(v.x, v.y, h01, l01);
    split2(v.z, v.w, h23, l23);
    uint2 hh = make_uint2(h01, h23), ll = make_uint2(l01, l23);
    size_t base = (size_t)m * K3 + k4;
    *(uint2*)&g_Xp[base] = hh;
    *(uint2*)&g_Xp[base + K_DIM] = hh;
    *(uint2*)&g_Xp[base + 2 * K_DIM] = ll;
}

// ---------------------------------------------------------------------------
// Precompute: W [K][N] f32 -> Wt [N][3K] bf16 = [hi | lo | hi]  (transposed)
// 32x32 tiles through shared.
// ---------------------------------------------------------------------------
__global__ __launch_bounds__(256) void split_w(const float* __restrict__ W) {
    __shared__ float ts[32][33];
    const int k0 = blockIdx.x * 32, n0 = blockIdx.y * 32;
    const int r = threadIdx.x >> 5, c = threadIdx.x & 31;
#pragma unroll
    for (int i = 0; i < 4; i++)
        ts[r + 8 * i][c] = W[(size_t)(k0 + r + 8 * i) * N_TOT + n0 + c];
    __syncthreads();
#pragma unroll
    for (int i = 0; i < 4; i++) {
        int n = n0 + r + 8 * i;
        float f = ts[c][r + 8 * i];
        __nv_bfloat16 hb = __float2bfloat16_rn(f);
        __nv_bfloat16 lb = __float2bfloat16_rn(f - __bfloat162float(hb));
        size_t base = (size_t)n * K3 + k0 + c;
        g_Wt[base] = hb;
        g_Wt[base + K_DIM] = lb;
        g_Wt[base + 2 * K_DIM] = hb;
    }
}

// ---------------------------------------------------------------------------
// Stage 1 GEMM: qkv = Xp @ Wt^T + b (plain bf16 MMA GEMM, K'=3072),
// scatter epilogue to Q/K/V.  128x128 block, BK=32, 256 thr = 8 warps,
// warp tile 64x32 (4 m-frags x 4 n-frags), ldmatrix + cp.async 2-stage.
// ---------------------------------------------------------------------------
__global__ __launch_bounds__(256, 2) void qkv_gemm_bf16(const float* __restrict__ bias) {
    __shared__ __align__(16) __nv_bfloat16 As[2][GBM][GBK + APAD];  // 20 KB
    __shared__ __align__(16) __nv_bfloat16 Bs[2][GBN][GBK + APAD];  // 20 KB

    const int tid = threadIdx.x;
    const int wid = tid >> 5, lane = tid & 31;
    const int wm = wid >> 2, wn = wid & 3;          // 2 x 4 warp grid
    const int q = lane >> 3, rr = lane & 7;
    const int bm = blockIdx.y * GBM, bn = blockIdx.x * GBN;

    float acc[4][4][4];
#pragma unroll
    for (int i = 0; i < 4; i++)
#pragma unroll
        for (int j = 0; j < 4; j++)
#pragma unroll
            for (int k = 0; k < 4; k++) acc[i][j][k] = 0.f;

    auto issue = [&](int t, int s) {
#pragma unroll
        for (int it = 0; it < 2; it++) {
            int idx = tid + it * 256;
            int row = idx >> 2, seg = (idx & 3) << 3;      // 4 x 16B per row
            cp16(&As[s][row][seg], &g_Xp[(size_t)(bm + row) * K3 + t * GBK + seg]);
            cp16(&Bs[s][row][seg], &g_Wt[(size_t)(bn + row) * K3 + t * GBK + seg]);
        }
        asm volatile("cp.async.commit_group;" ::: "memory");
    };

    issue(0, 0);
    for (int t = 0; t < NITER; t++) {
        const int buf = t & 1;
        asm volatile("cp.async.wait_group 0;" ::: "memory");
        __syncthreads();
        if (t + 1 < NITER) issue(t + 1, buf ^ 1);

#pragma unroll
        for (int ks = 0; ks < 2; ks++) {
            uint32_t a[4][4], bb[2][4];
#pragma unroll
            for (int mf = 0; mf < 4; mf++) {
                int arow = wm * 64 + mf * 16 + (q & 1) * 8 + rr;
                int acol = ks * 16 + (q >> 1) * 8;
                ldsm_x4(a[mf], &As[buf][arow][acol]);
            }
#pragma unroll
            for (int nh = 0; nh < 2; nh++) {
                int brow = wn * 32 + nh * 16 + (q >> 1) * 8 + rr;
                int bcol = ks * 16 + (q & 1) * 8;
                ldsm_x4(bb[nh], &Bs[buf][brow][bcol]);
            }
#pragma unroll
            for (int mf = 0; mf < 4; mf++)
#pragma unroll
                for (int nf = 0; nf < 4; nf++)
                    mma_bf16(acc[mf][nf], a[mf], &bb[nf >> 1][(nf & 1) * 2]);
        }
    }

    // Epilogue: bias + decode jc = h*192 + d*3 + cc, scatter into Q/K/V.
    const int r2 = lane >> 2, c2 = lane & 3;
#pragma unroll
    for (int nf = 0; nf < 4; nf++) {
#pragma unroll
        for (int i1 = 0; i1 < 2; i1++) {
            int jc = bn + wn * 32 + nf * 8 + c2 * 2 + i1;
            float bv = __ldg(&bias[jc]);
            int cc = jc % 3;
            int hd = jc / 3;
            int d = hd & 63, h = hd >> 6;
            float* dst = (cc == 0) ? g_Q : (cc == 1) ? g_K : g_V;
#pragma unroll
            for (int mf = 0; mf < 4; mf++)
#pragma unroll
                for (int i2 = 0; i2 < 2; i2++) {
                    int m = bm + wm * 64 + mf * 16 + r2 + i2 * 8;
                    int b = m >> 11, n = m & 2047;
                    dst[(((b << 4) + h) * SEQ + n) * HD + d] =
                        acc[mf][nf][i2 * 2 + i1] + bv;
                }
        }
    }
}

// ---------------------------------------------------------------------------
// Stage 2: per (bh, split): partial K^T V over a 256-row n-chunk.
// ---------------------------------------------------------------------------
__global__ __launch_bounds__(256) void ktv_partial() {
    const int sp = blockIdx.x, bh = blockIdx.y;
    const float* Kp = g_K + bh * SEQ * HD;
    const float* Vp = g_V + bh * SEQ * HD;
    __shared__ float Ks[32][64];
    __shared__ float Vs[32][64];
    const int tid = threadIdx.x;
    const int d1 = (tid >> 4) << 2;
    const int d2 = (tid & 15) << 2;
    float acc[4][4] = {};

    const int nbase = sp * (SEQ / NSPLIT);
    for (int n0 = nbase; n0 < nbase + SEQ / NSPLIT; n0 += 32) {
#pragma unroll
        for (int i = 0; i < 2; i++) {
            int idx = tid + i * 256;
            int rw = idx >> 4, c4 = (idx & 15) << 2;
            *(float4*)&Ks[rw][c4] = *(const float4*)&Kp[(n0 + rw) * HD + c4];
            *(float4*)&Vs[rw][c4] = *(const float4*)&Vp[(n0 + rw) * HD + c4];
        }
        __syncthreads();
#pragma unroll
        for (int n = 0; n < 32; n++) {
            float4 a = *(float4*)&Ks[n][d1];
            float4 b = *(float4*)&Vs[n][d2];
            float av[4] = {a.x, a.y, a.z, a.w};
            float bv[4] = {b.x, b.y, b.z, b.w};
#pragma unroll
            for (int i = 0; i < 4; i++)
#pragma unroll
                for (int j = 0; j < 4; j++)
                    acc[i][j] = fmaf(av[i], bv[j], acc[i][j]);
        }
        __syncthreads();
    }
#pragma unroll
    for (int i = 0; i < 4; i++)
#pragma unroll
        for (int j = 0; j < 4; j++)
            g_KtVp[((bh * NSPLIT + sp) * HD + d1 + i) * HD + d2 + j] = acc[i][j];
}

// ---------------------------------------------------------------------------
// Stage 3: reduce the NSPLIT partials, fold in scale = 32.
// ---------------------------------------------------------------------------
__global__ __launch_bounds__(256) void ktv_reduce() {
    int i = blockIdx.x * 256 + threadIdx.x;
    int bh = i >> 12, rc = i & 4095;
    float s = 0.f;
#pragma unroll
    for (int sp = 0; sp < NSPLIT; sp++)
        s += g_KtVp[(bh * NSPLIT + sp) * 4096 + rc];
    g_KtV[i] = 32.0f * s;
}

// ---------------------------------------------------------------------------
// Stage 4: out[bh][n][d] = Q[bh][n][:] @ KtV[bh][:][d]
// ---------------------------------------------------------------------------
__global__ __launch_bounds__(256) void out_gemm(float* __restrict__ out) {
    const int bh = blockIdx.y;
    const int n0 = blockIdx.x * 64;
    __shared__ float Qs[64][64];
    __shared__ float Ms[64][64];
    const int tid = threadIdx.x;

#pragma unroll
    for (int i = 0; i < 4; i++) {
        int idx = tid + i * 256;
        int rw = idx >> 4, c4 = (idx & 15) << 2;
        *(float4*)&Ms[rw][c4] = *(const float4*)&g_KtV[(bh * HD + rw) * HD + c4];
        *(float4*)&Qs[rw][c4] = *(const float4*)&g_Q[(bh * SEQ + n0 + rw) * HD + c4];
    }
    __syncthreads();

    const int r0 = (tid >> 4) << 2;
    const int c0 = (tid & 15) << 2;
    float acc[4][4] = {};
#pragma unroll
    for (int e = 0; e < 64; e++) {
        float4 b = *(float4*)&Ms[e][c0];
        float bv[4] = {b.x, b.y, b.z, b.w};
        float av[4] = {Qs[r0][e], Qs[r0 + 1][e], Qs[r0 + 2][e], Qs[r0 + 3][e]};
#pragma unroll
        for (int i = 0; i < 4; i++)
#pragma unroll
            for (int j = 0; j < 4; j++)
                acc[i][j] = fmaf(av[i], bv[j], acc[i][j]);
    }
#pragma unroll
    for (int i = 0; i < 4; i++) {
        float4 v = make_float4(acc[i][0], acc[i][1], acc[i][2], acc[i][3]);
        *(float4*)&out[(bh * SEQ + n0 + r0 + i) * HD + c0] = v;
    }
}

// ---------------------------------------------------------------------------
extern "C" void kernel_launch(void* const* d_in, const int* in_sizes, int n_in,
                              void* d_out, int out_size) {
    const float* x = (const float*)d_in[0];   // [4,2048,1024]
    const float* W = (const float*)d_in[1];   // [1024,3072]
    const float* b = (const float*)d_in[2];   // [3072]
    float* out = (float*)d_out;               // [4,16,2048,64]

    split_x<<<(M_TOT * K_DIM) / 1024, 256>>>(x);
    split_w<<<dim3(K_DIM / 32, N_TOT / 32), 256>>>(W);
    qkv_gemm_bf16<<<dim3(N_TOT / GBN, M_TOT / GBM), 256>>>(b);
    ktv_partial<<<dim3(NSPLIT, BH), 256>>>();
    ktv_reduce<<<(BH * HD * HD) / 256, 256>>>();
    out_gemm<<<dim3(SEQ / 64, BH), 256>>>(out);
}

// round 5
// speedup vs baseline: 5.0901x; 2.7717x over previous
#include <cuda_runtime.h>
#include <cuda_bf16.h>
#include <cstdint>

// Shapes: x [4,2048,1024] f32, W [1024,3072] f32, b [3072] f32
// out [4,16,2048,64] f32 = scale * Q (K^T V),  scale = 32
#define M_TOT 8192
#define K_DIM 1024
#define N_TOT 3072
#define K3    3072        // 3*K: [hi|hi|lo] x  vs  [hi|lo|hi] w
#define BH    64
#define SEQ   2048
#define HD    64
#define NSPLIT 16

// ---- stage-1 geometry (shared by both paths) ----
#define TBM 256
#define TBN 256
#define CHUNK 64                 // bf16 k-elems per stage = 128B rows (SW128 atom)
#define NCHUNK (K3 / CHUNK)      // 48
#define STAGES 3
#define A_BYTES (TBM * 128)
#define B_BYTES (TBN * 128)
#define STAGE_BYTES (A_BYTES + B_BYTES)
#define QKV_SMEM (1024 + 1024 + STAGES * STAGE_BYTES)   // 198656
#define IDESC_BF16 0x08400490u   // F32 acc | aBF16 | bBF16 | N=256 | M=128

// fallback tile params
#define GBK 32
#define APAD 8

// Device-pass feature gate: tcgen05 only on arch-specific ('a') targets.
#if defined(__CUDA_ARCH__) && (defined(__CUDA_ARCH_FEAT_SM103_ALL) || \
    defined(__CUDA_ARCH_FEAT_SM100_ALL) || defined(__CUDA_ARCH_SPECIFIC__))
#define USE_TC 1
#else
#define USE_TC 0
#endif

// Scratch (device globals; no runtime allocation allowed)
__device__ __nv_bfloat16 g_Xp[(size_t)M_TOT * K3];   // 50.3 MB
__device__ __nv_bfloat16 g_Wt[(size_t)N_TOT * K3];   // 18.9 MB
__device__ float g_Q[BH * SEQ * HD];                 // 32 MB
__device__ float g_K[BH * SEQ * HD];                 // 32 MB
__device__ float g_V[BH * SEQ * HD];                 // 32 MB
__device__ float g_KtVp[BH * NSPLIT * HD * HD];      // 16 MB
__device__ float g_KtV[BH * HD * HD];                // 1 MB

// ---------------------------------------------------------------------------
// common helpers
// ---------------------------------------------------------------------------
__device__ __forceinline__ void split2(float a, float b, uint32_t& hi, uint32_t& lo) {
    __nv_bfloat16 ah = __float2bfloat16_rn(a);
    __nv_bfloat16 bh = __float2bfloat16_rn(b);
    __nv_bfloat16 al = __float2bfloat16_rn(a - __bfloat162float(ah));
    __nv_bfloat16 bl = __float2bfloat16_rn(b - __bfloat162float(bh));
    hi = (uint32_t)(*reinterpret_cast<uint16_t*>(&ah)) |
         ((uint32_t)(*reinterpret_cast<uint16_t*>(&bh)) << 16);
    lo = (uint32_t)(*reinterpret_cast<uint16_t*>(&al)) |
         ((uint32_t)(*reinterpret_cast<uint16_t*>(&bl)) << 16);
}

__device__ __forceinline__ void cp16s(uint32_t smem_addr, const void* gmem) {
    asm volatile("cp.async.cg.shared.global [%0], [%1], 16;" :: "r"(smem_addr), "l"(gmem));
}

#if USE_TC
__device__ __forceinline__ uint32_t elect_one_pred() {
    uint32_t pred;
    asm volatile("{\n\t.reg .pred p;\n\telect.sync _|p, 0xFFFFFFFF;\n\t"
                 "selp.b32 %0, 1, 0, p;\n\t}" : "=r"(pred));
    return pred;
}

static constexpr uint64_t DESC_BASE_SW128 =
    (uint64_t(2) << 61) | (uint64_t(1) << 46) | (uint64_t(64) << 32) | (uint64_t(1) << 16);
__device__ __forceinline__ uint64_t make_desc(uint32_t addr) {
    return DESC_BASE_SW128 | ((uint64_t)(addr >> 4) & 0x3FFF);
}

__device__ __forceinline__ void mma_f16_ss(uint32_t d, uint64_t ad, uint64_t bd,
                                           uint32_t idesc, uint32_t en) {
    asm volatile(
        "{\n\t.reg .pred p;\n\tsetp.ne.u32 p, %5, 0;\n\t"
        "tcgen05.mma.cta_group::1.kind::f16 [%0], %1, %2, %3, {%4,%4,%4,%4}, p;\n\t}"
        :: "r"(d), "l"(ad), "l"(bd), "r"(idesc), "r"(0u), "r"(en) : "memory");
}

__device__ __forceinline__ void mbar_init(uint32_t a, uint32_t cnt) {
    asm volatile("mbarrier.init.shared.b64 [%0], %1;" :: "r"(a), "r"(cnt) : "memory");
}
__device__ __forceinline__ void mbar_wait(uint32_t a, uint32_t parity) {
    asm volatile(
        "{\n\t.reg .pred P;\n\tLAB_%=:\n\t"
        "mbarrier.try_wait.parity.acquire.cta.shared::cta.b64 P, [%0], %1;\n\t"
        "@!P bra LAB_%=;\n\t}" :: "r"(a), "r"(parity) : "memory");
}
__device__ __forceinline__ void tc_commit(uint32_t mbar) {
    asm volatile(
        "tcgen05.commit.cta_group::1.mbarrier::arrive::one.shared::cluster.b64 [%0];"
        :: "r"(mbar) : "memory");
}

#define LDTM_X32(r, a)                                                         \
    asm volatile("tcgen05.ld.sync.aligned.32x32b.x32.b32 "                     \
        "{%0,%1,%2,%3,%4,%5,%6,%7,%8,%9,%10,%11,%12,%13,%14,%15,"              \
        "%16,%17,%18,%19,%20,%21,%22,%23,%24,%25,%26,%27,%28,%29,%30,%31},"    \
        "[%32];"                                                               \
        : "=r"((r)[0]),"=r"((r)[1]),"=r"((r)[2]),"=r"((r)[3]),                 \
          "=r"((r)[4]),"=r"((r)[5]),"=r"((r)[6]),"=r"((r)[7]),                 \
          "=r"((r)[8]),"=r"((r)[9]),"=r"((r)[10]),"=r"((r)[11]),               \
          "=r"((r)[12]),"=r"((r)[13]),"=r"((r)[14]),"=r"((r)[15]),             \
          "=r"((r)[16]),"=r"((r)[17]),"=r"((r)[18]),"=r"((r)[19]),             \
          "=r"((r)[20]),"=r"((r)[21]),"=r"((r)[22]),"=r"((r)[23]),             \
          "=r"((r)[24]),"=r"((r)[25]),"=r"((r)[26]),"=r"((r)[27]),             \
          "=r"((r)[28]),"=r"((r)[29]),"=r"((r)[30]),"=r"((r)[31])              \
        : "r"(a))
#else
__device__ __forceinline__ void mma_bf16(float* c, const uint32_t* a, const uint32_t* b) {
    asm volatile(
        "mma.sync.aligned.m16n8k16.row.col.f32.bf16.bf16.f32 "
        "{%0,%1,%2,%3}, {%4,%5,%6,%7}, {%8,%9}, {%0,%1,%2,%3};"
        : "+f"(c[0]), "+f"(c[1]), "+f"(c[2]), "+f"(c[3])
        : "r"(a[0]), "r"(a[1]), "r"(a[2]), "r"(a[3]), "r"(b[0]), "r"(b[1]));
}
__device__ __forceinline__ void ldsm_x4(uint32_t* r, const void* p) {
    uint32_t a = (uint32_t)__cvta_generic_to_shared(p);
    asm volatile("ldmatrix.sync.aligned.m8n8.x4.shared.b16 {%0,%1,%2,%3}, [%4];"
                 : "=r"(r[0]), "=r"(r[1]), "=r"(r[2]), "=r"(r[3]) : "r"(a));
}
#endif

// ---------------------------------------------------------------------------
// Precompute: x [M][K] f32 -> Xp [M][3K] bf16 = [hi | hi | lo]
// ---------------------------------------------------------------------------
__global__ __launch_bounds__(256) void split_x(const float* __restrict__ x) {
    int i = blockIdx.x * 256 + threadIdx.x;
    int m = i >> 8, k4 = (i & 255) << 2;
    float4 v = *(const float4*)&x[(size_t)m * K_DIM + k4];
    uint32_t h01, l01, h23, l23;
    split2(v.x, v.y, h01, l01);
    split2(v.z, v.w, h23, l23);
    uint2 hh = make_uint2(h01, h23), ll = make_uint2(l01, l23);
    size_t base = (size_t)m * K3 + k4;
    *(uint2*)&g_Xp[base] = hh;
    *(uint2*)&g_Xp[base + K_DIM] = hh;
    *(uint2*)&g_Xp[base + 2 * K_DIM] = ll;
}

// ---------------------------------------------------------------------------
// Precompute: W [K][N] f32 -> Wt [N][3K] bf16 = [hi | lo | hi]  (transposed)
// ---------------------------------------------------------------------------
__global__ __launch_bounds__(256) void split_w(const float* __restrict__ W) {
    __shared__ float ts[32][33];
    const int k0 = blockIdx.x * 32, n0 = blockIdx.y * 32;
    const int r = threadIdx.x >> 5, c = threadIdx.x & 31;
#pragma unroll
    for (int i = 0; i < 4; i++)
        ts[r + 8 * i][c] = W[(size_t)(k0 + r + 8 * i) * N_TOT + n0 + c];
    __syncthreads();
#pragma unroll
    for (int i = 0; i < 4; i++) {
        int n = n0 + r + 8 * i;
        float f = ts[c][r + 8 * i];
        __nv_bfloat16 hb = __float2bfloat16_rn(f);
        __nv_bfloat16 lb = __float2bfloat16_rn(f - __bfloat162float(hb));
        size_t base = (size_t)n * K3 + k0 + c;
        g_Wt[base] = hb;
        g_Wt[base + K_DIM] = lb;
        g_Wt[base + 2 * K_DIM] = hb;
    }
}

// ---------------------------------------------------------------------------
// Stage 1: qkv = Xp @ Wt^T + bias, scatter to Q/K/V.
// Block tile 256x256, grid (12, 32), 256 threads, 194KB dynamic smem.
// Body: tcgen05 (arch-specific pass) OR mma.sync quadrants (generic pass).
// ---------------------------------------------------------------------------
extern __shared__ char dynsmem[];

__global__ __launch_bounds__(256, 1) void qkv_gemm(const float* __restrict__ bias) {
#if USE_TC
    const int tid = threadIdx.x, wid = tid >> 5, lane = tid & 31;
    const int bm = blockIdx.y * TBM, bn = blockIdx.x * TBN;

    uint32_t sb_raw = (uint32_t)__cvta_generic_to_shared(dynsmem);
    uint32_t s0 = (sb_raw + 1023) & ~1023u;
    uint32_t tiles = s0 + 1024;

    if (tid == 0) {
        mbar_init(s0 + 8, 1);
        mbar_init(s0 + 16, 1);
        mbar_init(s0 + 24, 1);
        mbar_init(s0 + 32, 1);
    }
    if (wid == 0)
        asm volatile("tcgen05.alloc.cta_group::1.sync.aligned.shared::cta.b32 [%0], %1;"
                     :: "r"(s0), "r"(512u) : "memory");
    __syncthreads();
    uint32_t tmem;
    asm volatile("ld.shared.b32 %0, [%1];" : "=r"(tmem) : "r"(s0));

    auto load_chunk = [&](int t) {
        const int buf = t % STAGES;
        const uint32_t abase = tiles + buf * STAGE_BYTES;
        const uint32_t bbase = abase + A_BYTES;
        const __nv_bfloat16* ag = &g_Xp[(size_t)bm * K3 + t * CHUNK];
        const __nv_bfloat16* bg = &g_Wt[(size_t)bn * K3 + t * CHUNK];
#pragma unroll
        for (int i = 0; i < 8; i++) {
            int idx = tid + i * 256;
            int r = idx >> 3, s = idx & 7;
            cp16s(abase + (r << 7) + ((s ^ (r & 7)) << 4), ag + (size_t)r * K3 + s * 8);
        }
#pragma unroll
        for (int i = 0; i < 8; i++) {
            int idx = tid + i * 256;
            int r = idx >> 3, s = idx & 7;
            cp16s(bbase + (r << 7) + ((s ^ (r & 7)) << 4), bg + (size_t)r * K3 + s * 8);
        }
        asm volatile("cp.async.commit_group;" ::: "memory");
    };

    load_chunk(0);
    load_chunk(1);

    for (int t = 0; t < NCHUNK; t++) {
        const int buf = t % STAGES;
        if (t < NCHUNK - 1)
            asm volatile("cp.async.wait_group 1;" ::: "memory");
        else
            asm volatile("cp.async.wait_group 0;" ::: "memory");
        __syncthreads();

        if (wid == 0 && elect_one_pred()) {
            asm volatile("fence.proxy.async.shared::cta;" ::: "memory");
            const uint32_t ab = tiles + buf * STAGE_BYTES;
            uint64_t a0 = make_desc(ab);
            uint64_t a1 = make_desc(ab + 16384);     // rows 128..255 of A
            uint64_t bd = make_desc(ab + A_BYTES);
#pragma unroll
            for (int k = 0; k < 4; k++) {
                uint32_t en = (t > 0 || k > 0) ? 1u : 0u;
                mma_f16_ss(tmem,       a0 + k * 2, bd + k * 2, IDESC_BF16, en);
                mma_f16_ss(tmem + 256, a1 + k * 2, bd + k * 2, IDESC_BF16, en);
            }
            tc_commit(s0 + 8 + 8 * buf);
        }

        const int c = t + 2;
        if (c < NCHUNK) {
            if (c >= STAGES) {
                uint32_t par = (uint32_t)((c / 3 - 1) & 1);
                mbar_wait(s0 + 8 + 8 * (c % 3), par);
            }
            load_chunk(c);
        }
    }

    if (wid == 0 && elect_one_pred()) tc_commit(s0 + 32);
    mbar_wait(s0 + 32, 0);
    asm volatile("tcgen05.fence::after_thread_sync;" ::: "memory");

    // Epilogue: LDTM + per-warp smem transpose + bias + scatter.
    const int tile = wid >> 2;
    const int m = bm + tile * 128 + (wid & 3) * 32 + lane;
    const int b = m >> 11;
    const int nrow0 = (bm & 2047) + tile * 128 + (wid & 3) * 32;
    float* epi = (float*)(dynsmem + (s0 - sb_raw) + 1024) + wid * (32 * 33);

    for (int cb = 0; cb < 8; cb++) {
        uint32_t r[32];
        LDTM_X32(r, tmem + tile * 256 + cb * 32);
        asm volatile("tcgen05.wait::ld.sync.aligned;" ::: "memory");

        int jc = bn + cb * 32 + lane;
        float bv = bias[jc];
        int cc = jc % 3;
        int hdv = jc / 3;
        int d = hdv & 63, h = hdv >> 6;
        float* dst = (cc == 0) ? g_Q : (cc == 1) ? g_K : g_V;
        size_t colbase = ((size_t)((b << 4) + h) * SEQ) * HD + d;

        __syncwarp();
#pragma unroll
        for (int j = 0; j < 32; j++) epi[j * 33 + lane] = __uint_as_float(r[j]);
        __syncwarp();
#pragma unroll
        for (int rj = 0; rj < 32; rj++) {
            float v = epi[lane * 33 + rj] + bv;
            dst[colbase + (size_t)(nrow0 + rj) * HD] = v;
        }
        __syncwarp();
    }

    __syncthreads();
    if (wid == 0) {
        asm volatile("tcgen05.relinquish_alloc_permit.cta_group::1.sync.aligned;");
        asm volatile("tcgen05.dealloc.cta_group::1.sync.aligned.b32 %0, %1;"
                     :: "r"(tmem), "r"(512u));
    }
#else
    // ---------------- fallback: mma.sync over 2x2 quadrants of 256x256 -----
    typedef __nv_bfloat16 RowA[128][GBK + APAD];
    RowA* As = (RowA*)dynsmem;                                    // [2][128][40]
    RowA* Bs = (RowA*)(dynsmem + 2 * 128 * (GBK + APAD) * 2);     // [2][128][40]

    const int tid = threadIdx.x;
    const int wid = tid >> 5, lane = tid & 31;
    const int wm = wid >> 2, wn = wid & 3;
    const int q = lane >> 3, rr = lane & 7;
    const int r2 = lane >> 2, c2 = lane & 3;

    for (int mq = 0; mq < 2; mq++)
        for (int nq = 0; nq < 2; nq++) {
            const int bm = blockIdx.y * TBM + mq * 128;
            const int bn = blockIdx.x * TBN + nq * 128;
            __syncthreads();

            float acc[4][4][4];
#pragma unroll
            for (int i = 0; i < 4; i++)
#pragma unroll
                for (int j = 0; j < 4; j++)
#pragma unroll
                    for (int k = 0; k < 4; k++) acc[i][j][k] = 0.f;

            auto issue = [&](int t, int s) {
#pragma unroll
                for (int it = 0; it < 2; it++) {
                    int idx = tid + it * 256;
                    int row = idx >> 2, seg = (idx & 3) << 3;
                    cp16s((uint32_t)__cvta_generic_to_shared(&As[s][row][seg]),
                          &g_Xp[(size_t)(bm + row) * K3 + t * GBK + seg]);
                    cp16s((uint32_t)__cvta_generic_to_shared(&Bs[s][row][seg]),
                          &g_Wt[(size_t)(bn + row) * K3 + t * GBK + seg]);
                }
                asm volatile("cp.async.commit_group;" ::: "memory");
            };

            issue(0, 0);
            const int NIT = K3 / GBK;
            for (int t = 0; t < NIT; t++) {
                const int buf = t & 1;
                asm volatile("cp.async.wait_group 0;" ::: "memory");
                __syncthreads();
                if (t + 1 < NIT) issue(t + 1, buf ^ 1);

#pragma unroll
                for (int ks = 0; ks < 2; ks++) {
                    uint32_t a[4][4], bb[2][4];
#pragma unroll
                    for (int mf = 0; mf < 4; mf++) {
                        int arow = wm * 64 + mf * 16 + (q & 1) * 8 + rr;
                        int acol = ks * 16 + (q >> 1) * 8;
                        ldsm_x4(a[mf], &As[buf][arow][acol]);
                    }
#pragma unroll
                    for (int nh = 0; nh < 2; nh++) {
                        int brow = wn * 32 + nh * 16 + (q >> 1) * 8 + rr;
                        int bcol = ks * 16 + (q & 1) * 8;
                        ldsm_x4(bb[nh], &Bs[buf][brow][bcol]);
                    }
#pragma unroll
                    for (int mf = 0; mf < 4; mf++)
#pragma unroll
                        for (int nf = 0; nf < 4; nf++)
                            mma_bf16(acc[mf][nf], a[mf], &bb[nf >> 1][(nf & 1) * 2]);
                }
                __syncthreads();
            }

#pragma unroll
            for (int nf = 0; nf < 4; nf++) {
#pragma unroll
                for (int i1 = 0; i1 < 2; i1++) {
                    int jc = bn + wn * 32 + nf * 8 + c2 * 2 + i1;
                    float bv = __ldg(&bias[jc]);
                    int cc = jc % 3;
                    int hdv = jc / 3;
                    int d = hdv & 63, h = hdv >> 6;
                    float* dst = (cc == 0) ? g_Q : (cc == 1) ? g_K : g_V;
#pragma unroll
                    for (int mf = 0; mf < 4; mf++)
#pragma unroll
                        for (int i2 = 0; i2 < 2; i2++) {
                            int m = bm + wm * 64 + mf * 16 + r2 + i2 * 8;
                            int b = m >> 11, n = m & 2047;
                            dst[(((b << 4) + h) * SEQ + n) * HD + d] =
                                acc[mf][nf][i2 * 2 + i1] + bv;
                        }
                }
            }
        }
#endif
}

// ---------------------------------------------------------------------------
// Stage 2: per (bh, split): partial K^T V over a 128-row n-chunk.
// ---------------------------------------------------------------------------
__global__ __launch_bounds__(256) void ktv_partial() {
    const int sp = blockIdx.x, bh = blockIdx.y;
    const float* Kp = g_K + bh * SEQ * HD;
    const float* Vp = g_V + bh * SEQ * HD;
    __shared__ float Ks[32][64];
    __shared__ float Vs[32][64];
    const int tid = threadIdx.x;
    const int d1 = (tid >> 4) << 2;
    const int d2 = (tid & 15) << 2;
    float acc[4][4] = {};

    const int nbase = sp * (SEQ / NSPLIT);
    for (int n0 = nbase; n0 < nbase + SEQ / NSPLIT; n0 += 32) {
#pragma unroll
        for (int i = 0; i < 2; i++) {
            int idx = tid + i * 256;
            int rw = idx >> 4, c4 = (idx & 15) << 2;
            *(float4*)&Ks[rw][c4] = *(const float4*)&Kp[(n0 + rw) * HD + c4];
            *(float4*)&Vs[rw][c4] = *(const float4*)&Vp[(n0 + rw) * HD + c4];
        }
        __syncthreads();
#pragma unroll
        for (int n = 0; n < 32; n++) {
            float4 a = *(float4*)&Ks[n][d1];
            float4 bq = *(float4*)&Vs[n][d2];
            float av[4] = {a.x, a.y, a.z, a.w};
            float bvv[4] = {bq.x, bq.y, bq.z, bq.w};
#pragma unroll
            for (int i = 0; i < 4; i++)
#pragma unroll
                for (int j = 0; j < 4; j++)
                    acc[i][j] = fmaf(av[i], bvv[j], acc[i][j]);
        }
        __syncthreads();
    }
#pragma unroll
    for (int i = 0; i < 4; i++)
#pragma unroll
        for (int j = 0; j < 4; j++)
            g_KtVp[((bh * NSPLIT + sp) * HD + d1 + i) * HD + d2 + j] = acc[i][j];
}

// ---------------------------------------------------------------------------
// Stage 3: reduce NSPLIT partials, fold in scale = 32.
// ---------------------------------------------------------------------------
__global__ __launch_bounds__(256) void ktv_reduce() {
    int i = blockIdx.x * 256 + threadIdx.x;
    int bh = i >> 12, rc = i & 4095;
    float s = 0.f;
#pragma unroll
    for (int sp = 0; sp < NSPLIT; sp++)
        s += g_KtVp[(bh * NSPLIT + sp) * 4096 + rc];
    g_KtV[i] = 32.0f * s;
}

// ---------------------------------------------------------------------------
// Stage 4: out[bh][n][d] = Q[bh][n][:] @ KtV[bh][:][d]
// ---------------------------------------------------------------------------
__global__ __launch_bounds__(256) void out_gemm(float* __restrict__ out) {
    const int bh = blockIdx.y;
    const int n0 = blockIdx.x * 64;
    __shared__ float Qs[64][64];
    __shared__ float Ms[64][64];
    const int tid = threadIdx.x;

#pragma unroll
    for (int i = 0; i < 4; i++) {
        int idx = tid + i * 256;
        int rw = idx >> 4, c4 = (idx & 15) << 2;
        *(float4*)&Ms[rw][c4] = *(const float4*)&g_KtV[(bh * HD + rw) * HD + c4];
        *(float4*)&Qs[rw][c4] = *(const float4*)&g_Q[(bh * SEQ + n0 + rw) * HD + c4];
    }
    __syncthreads();

    const int r0 = (tid >> 4) << 2;
    const int c0 = (tid & 15) << 2;
    float acc[4][4] = {};
#pragma unroll
    for (int e = 0; e < 64; e++) {
        float4 bq = *(float4*)&Ms[e][c0];
        float bv[4] = {bq.x, bq.y, bq.z, bq.w};
        float av[4] = {Qs[r0][e], Qs[r0 + 1][e], Qs[r0 + 2][e], Qs[r0 + 3][e]};
#pragma unroll
        for (int i = 0; i < 4; i++)
#pragma unroll
            for (int j = 0; j < 4; j++)
                acc[i][j] = fmaf(av[i], bv[j], acc[i][j]);
    }
#pragma unroll
    for (int i = 0; i < 4; i++) {
        float4 v = make_float4(acc[i][0], acc[i][1], acc[i][2], acc[i][3]);
        *(float4*)&out[(bh * SEQ + n0 + r0 + i) * HD + c0] = v;
    }
}

// ---------------------------------------------------------------------------
extern "C" void kernel_launch(void* const* d_in, const int* in_sizes, int n_in,
                              void* d_out, int out_size) {
    const float* x = (const float*)d_in[0];   // [4,2048,1024]
    const float* W = (const float*)d_in[1];   // [1024,3072]
    const float* b = (const float*)d_in[2];   // [3072]
    float* out = (float*)d_out;               // [4,16,2048,64]

    cudaFuncSetAttribute(qkv_gemm, cudaFuncAttributeMaxDynamicSharedMemorySize,
                         QKV_SMEM);

    split_x<<<(M_TOT * K_DIM) / 1024, 256>>>(x);
    split_w<<<dim3(K_DIM / 32, N_TOT / 32), 256>>>(W);
    qkv_gemm<<<dim3(N_TOT / TBN, M_TOT / TBM), 256, QKV_SMEM>>>(b);
    ktv_partial<<<dim3(NSPLIT, BH), 256>>>();
    ktv_reduce<<<(BH * HD * HD) / 256, 256>>>();
    out_gemm<<<dim3(SEQ / 64, BH), 256>>>(out);
}